// round 1
// baseline (speedup 1.0000x reference)
#include <cuda_runtime.h>
#include <math.h>

#define HIDDEN  2048
#define NHEADS  16
#define HDIM    128
#define BATCH   2
#define SEQ     2048
#define MTOK    (BATCH * SEQ)   // 4096

// ---------------- scratch (static device globals; no runtime allocation) ----
__device__ float g_q[(size_t)BATCH * NHEADS * SEQ * HDIM];  // [B,H,S,D] 32MB
__device__ float g_k[(size_t)BATCH * NHEADS * SEQ * HDIM];
__device__ float g_v[(size_t)BATCH * NHEADS * SEQ * HDIM];
__device__ float g_o[(size_t)MTOK * HIDDEN];                // [B*S, H*D] 32MB

// ============================================================================
// SGEMM (NT): C[m,n] = sum_k A[m,k] * B[n,k]
//   A: [M,K] row-major, B: [N,K] row-major (i.e. x @ W^T with W=[N,K])
//   MODE 0: C row-major [M,N]
//   MODE 1: C in [B, NHEADS, SEQ, HDIM] layout (for Q/K/V)
// 128x128 block tile, BK=8, 256 threads, 8x8 register tile.
// ============================================================================
template <int MODE>
__global__ __launch_bounds__(256) void sgemm_nt(const float* __restrict__ A,
                                                const float* __restrict__ B,
                                                float* __restrict__ C) {
    const int K = HIDDEN;
    const int N = HIDDEN;

    __shared__ float As[8][132];
    __shared__ float Bs[8][132];

    const int bm = blockIdx.y * 128;
    const int bn = blockIdx.x * 128;
    const int tid = threadIdx.x;

    const int lr = tid >> 1;         // 0..127 row within tile
    const int lc = (tid & 1) * 4;    // 0 or 4 : k offset
    const int tx = tid & 15;
    const int ty = tid >> 4;

    const float* Ap = A + (size_t)(bm + lr) * K + lc;
    const float* Bp = B + (size_t)(bn + lr) * K + lc;

    float acc[8][8];
#pragma unroll
    for (int i = 0; i < 8; i++)
#pragma unroll
        for (int j = 0; j < 8; j++) acc[i][j] = 0.0f;

    for (int k0 = 0; k0 < K; k0 += 8) {
        float4 a = *(const float4*)(Ap + k0);
        float4 b = *(const float4*)(Bp + k0);
        As[lc + 0][lr] = a.x; As[lc + 1][lr] = a.y;
        As[lc + 2][lr] = a.z; As[lc + 3][lr] = a.w;
        Bs[lc + 0][lr] = b.x; Bs[lc + 1][lr] = b.y;
        Bs[lc + 2][lr] = b.z; Bs[lc + 3][lr] = b.w;
        __syncthreads();

#pragma unroll
        for (int kk = 0; kk < 8; kk++) {
            float4 a0 = *(const float4*)&As[kk][ty * 8];
            float4 a1 = *(const float4*)&As[kk][ty * 8 + 4];
            float4 b0 = *(const float4*)&Bs[kk][tx * 8];
            float4 b1 = *(const float4*)&Bs[kk][tx * 8 + 4];
            float ar[8] = {a0.x, a0.y, a0.z, a0.w, a1.x, a1.y, a1.z, a1.w};
            float br[8] = {b0.x, b0.y, b0.z, b0.w, b1.x, b1.y, b1.z, b1.w};
#pragma unroll
            for (int i = 0; i < 8; i++)
#pragma unroll
                for (int j = 0; j < 8; j++) acc[i][j] += ar[i] * br[j];
        }
        __syncthreads();
    }

#pragma unroll
    for (int i = 0; i < 8; i++) {
        const int m = bm + ty * 8 + i;
#pragma unroll
        for (int j = 0; j < 8; j++) {
            const int n = bn + tx * 8 + j;
            const float v = acc[i][j];
            if (MODE == 0) {
                C[(size_t)m * N + n] = v;
            } else {
                const int b = m >> 11;       // m / SEQ
                const int s = m & (SEQ - 1);
                const int h = n >> 7;        // n / HDIM
                const int d = n & (HDIM - 1);
                C[((((size_t)b * NHEADS + h) * SEQ + s) << 7) + d] = v;
            }
        }
    }
}

// ============================================================================
// RoPE on Q and K in [B,H,S,D] layout. One block per (b,h,s), 64 threads
// handle rotation pairs (i, i+64). fp32 math mirrors the reference.
// ============================================================================
__global__ __launch_bounds__(64) void rope_kernel(float* __restrict__ q,
                                                  float* __restrict__ k) {
    const int idx = blockIdx.x;            // (b*NHEADS+h)*SEQ + s
    const int s = idx & (SEQ - 1);
    const int i = threadIdx.x;             // 0..63

    const float expo = (float)(2 * i) / 128.0f;
    const float inv = powf(10000.0f, -expo);
    const float ang = (float)s * inv;
    float sn, cs;
    sincosf(ang, &sn, &cs);

    float* pq = q + (size_t)idx * HDIM;
    float* pk = k + (size_t)idx * HDIM;

    const float q0 = pq[i], q1 = pq[i + 64];
    pq[i]      = q0 * cs - q1 * sn;
    pq[i + 64] = q1 * cs + q0 * sn;

    const float k0 = pk[i], k1 = pk[i + 64];
    pk[i]      = k0 * cs - k1 * sn;
    pk[i + 64] = k1 * cs + k0 * sn;
}

// ============================================================================
// Flash attention (fp32, online softmax).
//   grid: (SEQ/BQ, BATCH*NHEADS), block: 256 threads.
//   Q,K,V in [B,H,S,D]; output written token-major [B*S, H*D] for the final
//   projection.
// Stage 1: S = (Q*scale) @ K^T, 16x16 thread grid, 4x4 per thread.
// Stage 2: online softmax stats via 16-lane shfl reductions.
// Stage 3: P written into the K smem buffer; O += P @ V with 4x8 per thread.
// ============================================================================
#define FA_BQ 64
#define FA_BK 64
#define FA_PD 132   // padded row stride (floats)
#define FA_SMEM (3 * FA_BQ * FA_PD * 4)   // Qs + Ks(P) + Vs = 101376 bytes

__global__ __launch_bounds__(256) void flash_attn(const float* __restrict__ Q,
                                                  const float* __restrict__ K,
                                                  const float* __restrict__ V,
                                                  float* __restrict__ O) {
    extern __shared__ float sm[];
    float* Qs = sm;                          // FA_BQ * FA_PD
    float* Ks = sm + FA_BQ * FA_PD;          // FA_BK * FA_PD (reused for P)
    float* Vs = Ks + FA_BK * FA_PD;          // FA_BK * FA_PD

    const int bh = blockIdx.y;
    const int q0 = blockIdx.x * FA_BQ;
    const int tid = threadIdx.x;
    const int tx = tid & 15;
    const int ty = tid >> 4;

    const float scale = 0.08838834764831845f;   // 1/sqrt(128)

    // ---- load Q tile (scaled) ----
    {
        const float* Qg = Q + ((size_t)bh * SEQ + q0) * HDIM;
        const int row = tid >> 2;
        const int c0 = (tid & 3) * 4;
#pragma unroll
        for (int it = 0; it < 8; it++) {
            const int col = c0 + it * 16;
            float4 v = *(const float4*)(Qg + row * HDIM + col);
            v.x *= scale; v.y *= scale; v.z *= scale; v.w *= scale;
            *(float4*)&Qs[row * FA_PD + col] = v;
        }
    }

    float m_i[4], l_i[4], o[4][8];
#pragma unroll
    for (int i = 0; i < 4; i++) {
        m_i[i] = -1e30f;
        l_i[i] = 0.0f;
#pragma unroll
        for (int j = 0; j < 8; j++) o[i][j] = 0.0f;
    }

    for (int kt = 0; kt < SEQ / FA_BK; kt++) {
        const float* Kg = K + ((size_t)bh * SEQ + kt * FA_BK) * HDIM;
        const float* Vg = V + ((size_t)bh * SEQ + kt * FA_BK) * HDIM;

        __syncthreads();   // previous iteration's P/V reads (and Q write) done
        {
            const int row = tid >> 2;
            const int c0 = (tid & 3) * 4;
#pragma unroll
            for (int it = 0; it < 8; it++) {
                const int col = c0 + it * 16;
                *(float4*)&Ks[row * FA_PD + col] =
                    *(const float4*)(Kg + row * HDIM + col);
                *(float4*)&Vs[row * FA_PD + col] =
                    *(const float4*)(Vg + row * HDIM + col);
            }
        }
        __syncthreads();

        // ---- S = Qs @ Ks^T : rows ty*4+i, cols tx*4+j ----
        float s[4][4];
#pragma unroll
        for (int i = 0; i < 4; i++)
#pragma unroll
            for (int j = 0; j < 4; j++) s[i][j] = 0.0f;

        for (int k = 0; k < HDIM; k += 4) {
            float4 qv[4], kv[4];
#pragma unroll
            for (int i = 0; i < 4; i++)
                qv[i] = *(const float4*)&Qs[(ty * 4 + i) * FA_PD + k];
#pragma unroll
            for (int j = 0; j < 4; j++)
                kv[j] = *(const float4*)&Ks[(tx * 4 + j) * FA_PD + k];
#pragma unroll
            for (int i = 0; i < 4; i++)
#pragma unroll
                for (int j = 0; j < 4; j++)
                    s[i][j] += qv[i].x * kv[j].x + qv[i].y * kv[j].y +
                               qv[i].z * kv[j].z + qv[i].w * kv[j].w;
        }

        // ---- online softmax stats (per q row, reduce across 16 tx lanes) ----
#pragma unroll
        for (int i = 0; i < 4; i++) {
            float mx = fmaxf(fmaxf(s[i][0], s[i][1]), fmaxf(s[i][2], s[i][3]));
#pragma unroll
            for (int off = 8; off >= 1; off >>= 1)
                mx = fmaxf(mx, __shfl_xor_sync(0xffffffffu, mx, off));
            const float mn = fmaxf(m_i[i], mx);
            const float fi = expf(m_i[i] - mn);
            float rs = 0.0f;
#pragma unroll
            for (int j = 0; j < 4; j++) {
                s[i][j] = expf(s[i][j] - mn);
                rs += s[i][j];
            }
#pragma unroll
            for (int off = 8; off >= 1; off >>= 1)
                rs += __shfl_xor_sync(0xffffffffu, rs, off);
            l_i[i] = l_i[i] * fi + rs;
            m_i[i] = mn;
#pragma unroll
            for (int j = 0; j < 8; j++) o[i][j] *= fi;
        }

        __syncthreads();   // all Ks reads finished; safe to overwrite with P
#pragma unroll
        for (int i = 0; i < 4; i++)
            *(float4*)&Ks[(ty * 4 + i) * FA_PD + tx * 4] =
                make_float4(s[i][0], s[i][1], s[i][2], s[i][3]);
        __syncthreads();

        // ---- O += P @ V : rows ty*4+i, d-cols tx*8..tx*8+7 ----
        for (int k = 0; k < FA_BK; k++) {
            const float4 v0 = *(const float4*)&Vs[k * FA_PD + tx * 8];
            const float4 v1 = *(const float4*)&Vs[k * FA_PD + tx * 8 + 4];
#pragma unroll
            for (int i = 0; i < 4; i++) {
                const float pv = Ks[(ty * 4 + i) * FA_PD + k];
                o[i][0] += pv * v0.x; o[i][1] += pv * v0.y;
                o[i][2] += pv * v0.z; o[i][3] += pv * v0.w;
                o[i][4] += pv * v1.x; o[i][5] += pv * v1.y;
                o[i][6] += pv * v1.z; o[i][7] += pv * v1.w;
            }
        }
    }

    // ---- epilogue: O/l, write token-major [B*S, H*D] ----
    const int b = bh >> 4;
    const int h = bh & 15;
#pragma unroll
    for (int i = 0; i < 4; i++) {
        const float inv = 1.0f / l_i[i];
        const int m = b * SEQ + q0 + ty * 4 + i;
        const int col = h * HDIM + tx * 8;
        float4 r0 = make_float4(o[i][0] * inv, o[i][1] * inv,
                                o[i][2] * inv, o[i][3] * inv);
        float4 r1 = make_float4(o[i][4] * inv, o[i][5] * inv,
                                o[i][6] * inv, o[i][7] * inv);
        *(float4*)&O[(size_t)m * HIDDEN + col] = r0;
        *(float4*)&O[(size_t)m * HIDDEN + col + 4] = r1;
    }
}

// ============================================================================
// kernel_launch
// ============================================================================
extern "C" void kernel_launch(void* const* d_in, const int* in_sizes, int n_in,
                              void* d_out, int out_size) {
    (void)in_sizes; (void)n_in; (void)out_size;
    const float* x  = (const float*)d_in[0];
    const float* wq = (const float*)d_in[1];
    const float* wk = (const float*)d_in[2];
    const float* wv = (const float*)d_in[3];
    const float* wo = (const float*)d_in[4];
    float* out = (float*)d_out;

    float *q, *k, *v, *o;
    cudaGetSymbolAddress((void**)&q, g_q);
    cudaGetSymbolAddress((void**)&k, g_k);
    cudaGetSymbolAddress((void**)&v, g_v);
    cudaGetSymbolAddress((void**)&o, g_o);

    const dim3 gridP(HIDDEN / 128, MTOK / 128);   // (16, 32)

    sgemm_nt<1><<<gridP, 256>>>(x, wq, q);
    sgemm_nt<1><<<gridP, 256>>>(x, wk, k);
    sgemm_nt<1><<<gridP, 256>>>(x, wv, v);

    rope_kernel<<<BATCH * NHEADS * SEQ, 64>>>(q, k);

    cudaFuncSetAttribute(flash_attn,
                         cudaFuncAttributeMaxDynamicSharedMemorySize, FA_SMEM);
    flash_attn<<<dim3(SEQ / FA_BQ, BATCH * NHEADS), 256, FA_SMEM>>>(q, k, v, o);

    sgemm_nt<0><<<gridP, 256>>>(o, wo, out);
}

// round 2
// speedup vs baseline: 2.2858x; 2.2858x over previous
#include <cuda_runtime.h>
#include <cuda_fp16.h>
#include <math.h>
#include <stdint.h>

#define HIDDEN  2048
#define NHEADS  16
#define HDIM    128
#define BATCH   2
#define SEQ     2048
#define MTOK    (BATCH * SEQ)   // 4096

// ---------------- scratch (static device globals; no runtime allocation) ----
__device__ float g_q[(size_t)BATCH * NHEADS * SEQ * HDIM];  // [B,H,S,D]
__device__ float g_k[(size_t)BATCH * NHEADS * SEQ * HDIM];
__device__ float g_v[(size_t)BATCH * NHEADS * SEQ * HDIM];
__device__ float g_o[(size_t)MTOK * HIDDEN];                // [B*S, H*D]

// ---------------- helpers ---------------------------------------------------
__device__ __forceinline__ uint32_t pack_h2(__half a, __half b) {
    return (uint32_t)__half_as_ushort(a) | ((uint32_t)__half_as_ushort(b) << 16);
}
// split two floats into (hi half2, lo half2)
__device__ __forceinline__ void split2(float x, float y, uint32_t& hi, uint32_t& lo) {
    __half hx = __float2half_rn(x);
    __half hy = __float2half_rn(y);
    float rx = x - __half2float(hx);
    float ry = y - __half2float(hy);
    hi = pack_h2(hx, hy);
    lo = pack_h2(__float2half_rn(rx), __float2half_rn(ry));
}

__device__ __forceinline__ void mma16816(float* c, const uint32_t* a,
                                         uint32_t b0, uint32_t b1) {
    asm volatile(
        "mma.sync.aligned.m16n8k16.row.col.f32.f16.f16.f32 "
        "{%0,%1,%2,%3}, {%4,%5,%6,%7}, {%8,%9}, {%0,%1,%2,%3};\n"
        : "+f"(c[0]), "+f"(c[1]), "+f"(c[2]), "+f"(c[3])
        : "r"(a[0]), "r"(a[1]), "r"(a[2]), "r"(a[3]), "r"(b0), "r"(b1));
}

// ============================================================================
// Split-fp16 3-pass GEMM (NT): C[m,n] = sum_k A[m,k]*B[n,k], K=N=2048
// 128x128 block, BK=32, 256 threads (8 warps as 2x4), warp tile 64x32.
// MODE 0: C row-major.  MODE 1: C in [B,NHEADS,SEQ,HDIM].
// smem stride: 20 half2-words per row -> fragment loads conflict-free.
// ============================================================================
template <int MODE>
__global__ __launch_bounds__(256) void hgemm3(const float* __restrict__ A,
                                              const float* __restrict__ B,
                                              float* __restrict__ C) {
    __shared__ uint32_t Ah2[128 * 20];
    __shared__ uint32_t Al2[128 * 20];
    __shared__ uint32_t Bh2[128 * 20];
    __shared__ uint32_t Bl2[128 * 20];

    const int bm = blockIdx.y * 128;
    const int bn = blockIdx.x * 128;
    const int tid = threadIdx.x;
    const int w = tid >> 5, lane = tid & 31;
    const int g = lane >> 2, tg = lane & 3;
    const int wm = w >> 2;          // 0..1
    const int wn = w & 3;           // 0..3

    const int lrow = tid >> 1;          // 0..127
    const int kb = (tid & 1) * 16;      // 0 or 16

    const float* Ap = A + (size_t)(bm + lrow) * HIDDEN + kb;
    const float* Bp = B + (size_t)(bn + lrow) * HIDDEN + kb;

    float acc[4][4][4];
#pragma unroll
    for (int i = 0; i < 4; i++)
#pragma unroll
        for (int j = 0; j < 4; j++)
#pragma unroll
            for (int c = 0; c < 4; c++) acc[i][j][c] = 0.0f;

    for (int k0 = 0; k0 < HIDDEN; k0 += 32) {
        __syncthreads();
#pragma unroll
        for (int j = 0; j < 4; j++) {
            float4 va = *(const float4*)(Ap + k0 + j * 4);
            float4 vb = *(const float4*)(Bp + k0 + j * 4);
            uint32_t h0, l0, h1, l1;
            const int ad = lrow * 20 + (tid & 1) * 8 + j * 2;
            split2(va.x, va.y, h0, l0);
            split2(va.z, va.w, h1, l1);
            Ah2[ad] = h0; Ah2[ad + 1] = h1;
            Al2[ad] = l0; Al2[ad + 1] = l1;
            split2(vb.x, vb.y, h0, l0);
            split2(vb.z, vb.w, h1, l1);
            Bh2[ad] = h0; Bh2[ad + 1] = h1;
            Bl2[ad] = l0; Bl2[ad + 1] = l1;
        }
        __syncthreads();

#pragma unroll
        for (int ks = 0; ks < 2; ks++) {
            uint32_t ah[4][4], al[4][4];
#pragma unroll
            for (int mf = 0; mf < 4; mf++) {
                const int r = wm * 64 + mf * 16 + g;
                const int base = ks * 8 + tg;
                ah[mf][0] = Ah2[r * 20 + base];
                ah[mf][1] = Ah2[(r + 8) * 20 + base];
                ah[mf][2] = Ah2[r * 20 + base + 4];
                ah[mf][3] = Ah2[(r + 8) * 20 + base + 4];
                al[mf][0] = Al2[r * 20 + base];
                al[mf][1] = Al2[(r + 8) * 20 + base];
                al[mf][2] = Al2[r * 20 + base + 4];
                al[mf][3] = Al2[(r + 8) * 20 + base + 4];
            }
#pragma unroll
            for (int nf = 0; nf < 4; nf++) {
                const int n = wn * 32 + nf * 8 + g;
                const int base = ks * 8 + tg;
                const uint32_t bh0 = Bh2[n * 20 + base];
                const uint32_t bh1 = Bh2[n * 20 + base + 4];
                const uint32_t bl0 = Bl2[n * 20 + base];
                const uint32_t bl1 = Bl2[n * 20 + base + 4];
#pragma unroll
                for (int mf = 0; mf < 4; mf++) {
                    mma16816(acc[mf][nf], ah[mf], bh0, bh1);
                    mma16816(acc[mf][nf], al[mf], bh0, bh1);
                    mma16816(acc[mf][nf], ah[mf], bl0, bl1);
                }
            }
        }
    }

    // epilogue: c0:(g,2tg) c1:(g,2tg+1) c2:(g+8,2tg) c3:(g+8,2tg+1)
#pragma unroll
    for (int mf = 0; mf < 4; mf++) {
#pragma unroll
        for (int nf = 0; nf < 4; nf++) {
            const int n = bn + wn * 32 + nf * 8 + tg * 2;
#pragma unroll
            for (int half = 0; half < 2; half++) {
                const int m = bm + wm * 64 + mf * 16 + g + half * 8;
                const float2 vv = make_float2(acc[mf][nf][half * 2],
                                              acc[mf][nf][half * 2 + 1]);
                if (MODE == 0) {
                    *(float2*)&C[(size_t)m * HIDDEN + n] = vv;
                } else {
                    const int b = m >> 11;
                    const int s = m & (SEQ - 1);
                    const int h = n >> 7;
                    const int d = n & (HDIM - 1);
                    *(float2*)&C[((((size_t)b * NHEADS + h) * SEQ + s) << 7) + d] = vv;
                }
            }
        }
    }
}

// ============================================================================
// RoPE on Q and K in [B,H,S,D]; one block per (b,h,s), 64 threads.
// ============================================================================
__global__ __launch_bounds__(64) void rope_kernel(float* __restrict__ q,
                                                  float* __restrict__ k) {
    const int idx = blockIdx.x;
    const int s = idx & (SEQ - 1);
    const int i = threadIdx.x;

    const float expo = (float)(2 * i) / 128.0f;
    const float inv = powf(10000.0f, -expo);
    const float ang = (float)s * inv;
    float sn, cs;
    sincosf(ang, &sn, &cs);

    float* pq = q + (size_t)idx * HDIM;
    float* pk = k + (size_t)idx * HDIM;

    const float q0 = pq[i], q1 = pq[i + 64];
    pq[i]      = q0 * cs - q1 * sn;
    pq[i + 64] = q1 * cs + q0 * sn;

    const float k0 = pk[i], k1 = pk[i + 64];
    pk[i]      = k0 * cs - k1 * sn;
    pk[i + 64] = k1 * cs + k0 * sn;
}

// ============================================================================
// Flash attention, split-fp16 3-pass mma.
// grid (SEQ/128, B*H), 256 threads = 8 warps; warp w owns q rows [16w,16w+16).
// Q held in registers as A fragments (hi+lo). K tile 64 keys per iteration.
// smem (u32 words): Kh2[64*68] Kl2[64*68] Vh2[128*36] Vl2[128*36]
//                   P per warp: Ph2[16*36] Pl2[16*36]
// ============================================================================
#define AT_KH  0
#define AT_KL  (64 * 68)
#define AT_VH  (2 * 64 * 68)
#define AT_VL  (2 * 64 * 68 + 128 * 36)
#define AT_P   (2 * 64 * 68 + 2 * 128 * 36)
#define AT_SMEM_WORDS (AT_P + 8 * 2 * 16 * 36)
#define AT_SMEM_BYTES (AT_SMEM_WORDS * 4)

__global__ __launch_bounds__(256) void flash_attn_h(const float* __restrict__ Q,
                                                    const float* __restrict__ K,
                                                    const float* __restrict__ V,
                                                    float* __restrict__ O) {
    extern __shared__ uint32_t su[];
    uint32_t* Kh2 = su + AT_KH;
    uint32_t* Kl2 = su + AT_KL;
    uint32_t* Vh2 = su + AT_VH;
    uint32_t* Vl2 = su + AT_VL;

    const int tid = threadIdx.x;
    const int w = tid >> 5, lane = tid & 31;
    const int g = lane >> 2, tg = lane & 3;
    uint32_t* Ph2 = su + AT_P + w * (2 * 16 * 36);
    uint32_t* Pl2 = Ph2 + 16 * 36;

    const int bh = blockIdx.y;
    const int q0 = blockIdx.x * 128;
    const float sc = 0.08838834764831845f;   // 1/sqrt(128)

    // ---- load Q fragments directly from gmem (hi+lo), scaled --------------
    uint32_t qh[8][4], ql[8][4];
    {
        const float* Qg = Q + ((size_t)bh * SEQ + q0 + w * 16) * HDIM;
#pragma unroll
        for (int ks = 0; ks < 8; ks++) {
            const int c = ks * 16 + tg * 2;
            float2 x0 = *(const float2*)&Qg[g * HDIM + c];
            float2 x1 = *(const float2*)&Qg[(g + 8) * HDIM + c];
            float2 x2 = *(const float2*)&Qg[g * HDIM + c + 8];
            float2 x3 = *(const float2*)&Qg[(g + 8) * HDIM + c + 8];
            split2(x0.x * sc, x0.y * sc, qh[ks][0], ql[ks][0]);
            split2(x1.x * sc, x1.y * sc, qh[ks][1], ql[ks][1]);
            split2(x2.x * sc, x2.y * sc, qh[ks][2], ql[ks][2]);
            split2(x3.x * sc, x3.y * sc, qh[ks][3], ql[ks][3]);
        }
    }

    float m0 = -1e30f, m1 = -1e30f, l0 = 0.0f, l1 = 0.0f;
    float oacc[16][4];
#pragma unroll
    for (int nf = 0; nf < 16; nf++)
#pragma unroll
        for (int c = 0; c < 4; c++) oacc[nf][c] = 0.0f;

    for (int kt = 0; kt < SEQ / 64; kt++) {
        __syncthreads();   // previous iteration's smem reads complete

        // ---- load K tile (64x128) -> Kh2/Kl2 [key][d2], stride 68 ----
        {
            const float* Kg = K + ((size_t)bh * SEQ + kt * 64) * HDIM;
            const int row = tid >> 2;
            const int q4 = tid & 3;
#pragma unroll
            for (int i = 0; i < 8; i++) {
                const int d0 = q4 * 32 + i * 4;
                float4 v = *(const float4*)&Kg[row * HDIM + d0];
                uint32_t h0, lo0, h1, lo1;
                split2(v.x, v.y, h0, lo0);
                split2(v.z, v.w, h1, lo1);
                const int ad = row * 68 + d0 / 2;
                Kh2[ad] = h0; Kh2[ad + 1] = h1;
                Kl2[ad] = lo0; Kl2[ad + 1] = lo1;
            }
        }
        // ---- load V tile transposed -> Vh2/Vl2 [d][key2], stride 36 ----
        {
            const float* Vg = V + ((size_t)bh * SEQ + kt * 64) * HDIM;
            const int d = tid & 127;
            const int kbase = (tid >> 7) * 16;
#pragma unroll
            for (int j = 0; j < 16; j++) {
                const int key2 = kbase + j;
                const float a = Vg[(2 * key2) * HDIM + d];
                const float b = Vg[(2 * key2 + 1) * HDIM + d];
                uint32_t hi, lo;
                split2(a, b, hi, lo);
                Vh2[d * 36 + key2] = hi;
                Vl2[d * 36 + key2] = lo;
            }
        }
        __syncthreads();

        // ---- S = Q K^T for this warp's 16 q-rows x 64 keys ----
        float sacc[8][4];
#pragma unroll
        for (int nf = 0; nf < 8; nf++)
#pragma unroll
            for (int c = 0; c < 4; c++) sacc[nf][c] = 0.0f;

#pragma unroll
        for (int ks = 0; ks < 8; ks++) {
#pragma unroll
            for (int nf = 0; nf < 8; nf++) {
                const int ad = (nf * 8 + g) * 68 + ks * 8 + tg;
                const uint32_t bh0 = Kh2[ad], bh1 = Kh2[ad + 4];
                const uint32_t bl0 = Kl2[ad], bl1 = Kl2[ad + 4];
                mma16816(sacc[nf], qh[ks], bh0, bh1);
                mma16816(sacc[nf], ql[ks], bh0, bh1);
                mma16816(sacc[nf], qh[ks], bl0, bl1);
            }
        }

        // ---- online softmax (rows g and g+8; quad lanes share a row) ----
        float mx0 = -1e30f, mx1 = -1e30f;
#pragma unroll
        for (int nf = 0; nf < 8; nf++) {
            mx0 = fmaxf(mx0, fmaxf(sacc[nf][0], sacc[nf][1]));
            mx1 = fmaxf(mx1, fmaxf(sacc[nf][2], sacc[nf][3]));
        }
        mx0 = fmaxf(mx0, __shfl_xor_sync(0xffffffffu, mx0, 1));
        mx0 = fmaxf(mx0, __shfl_xor_sync(0xffffffffu, mx0, 2));
        mx1 = fmaxf(mx1, __shfl_xor_sync(0xffffffffu, mx1, 1));
        mx1 = fmaxf(mx1, __shfl_xor_sync(0xffffffffu, mx1, 2));

        const float mn0 = fmaxf(m0, mx0);
        const float mn1 = fmaxf(m1, mx1);
        const float fi0 = __expf(m0 - mn0);
        const float fi1 = __expf(m1 - mn1);
        m0 = mn0; m1 = mn1;

        float sum0 = 0.0f, sum1 = 0.0f;
#pragma unroll
        for (int nf = 0; nf < 8; nf++) {
            sacc[nf][0] = __expf(sacc[nf][0] - mn0);
            sacc[nf][1] = __expf(sacc[nf][1] - mn0);
            sacc[nf][2] = __expf(sacc[nf][2] - mn1);
            sacc[nf][3] = __expf(sacc[nf][3] - mn1);
            sum0 += sacc[nf][0] + sacc[nf][1];
            sum1 += sacc[nf][2] + sacc[nf][3];
        }
        sum0 += __shfl_xor_sync(0xffffffffu, sum0, 1);
        sum0 += __shfl_xor_sync(0xffffffffu, sum0, 2);
        sum1 += __shfl_xor_sync(0xffffffffu, sum1, 1);
        sum1 += __shfl_xor_sync(0xffffffffu, sum1, 2);
        l0 = l0 * fi0 + sum0;
        l1 = l1 * fi1 + sum1;

#pragma unroll
        for (int nf = 0; nf < 16; nf++) {
            oacc[nf][0] *= fi0; oacc[nf][1] *= fi0;
            oacc[nf][2] *= fi1; oacc[nf][3] *= fi1;
        }

        // ---- write P (warp-private region), hi+lo ----
#pragma unroll
        for (int nf = 0; nf < 8; nf++) {
            uint32_t hi, lo;
            split2(sacc[nf][0], sacc[nf][1], hi, lo);
            Ph2[g * 36 + nf * 4 + tg] = hi;
            Pl2[g * 36 + nf * 4 + tg] = lo;
            split2(sacc[nf][2], sacc[nf][3], hi, lo);
            Ph2[(g + 8) * 36 + nf * 4 + tg] = hi;
            Pl2[(g + 8) * 36 + nf * 4 + tg] = lo;
        }
        __syncwarp();

        // ---- O += P @ V ----
#pragma unroll
        for (int ks = 0; ks < 4; ks++) {
            uint32_t pa[4], pl[4];
            const int base = ks * 8 + tg;
            pa[0] = Ph2[g * 36 + base];
            pa[1] = Ph2[(g + 8) * 36 + base];
            pa[2] = Ph2[g * 36 + base + 4];
            pa[3] = Ph2[(g + 8) * 36 + base + 4];
            pl[0] = Pl2[g * 36 + base];
            pl[1] = Pl2[(g + 8) * 36 + base];
            pl[2] = Pl2[g * 36 + base + 4];
            pl[3] = Pl2[(g + 8) * 36 + base + 4];
#pragma unroll
            for (int nf = 0; nf < 16; nf++) {
                const int ad = (nf * 8 + g) * 36 + base;
                const uint32_t bh0 = Vh2[ad], bh1 = Vh2[ad + 4];
                const uint32_t bl0 = Vl2[ad], bl1 = Vl2[ad + 4];
                mma16816(oacc[nf], pa, bh0, bh1);
                mma16816(oacc[nf], pl, bh0, bh1);
                mma16816(oacc[nf], pa, bl0, bl1);
            }
        }
    }

    // ---- epilogue: O / l -> token-major [B*S, H*D] ----
    const int b = bh >> 4;
    const int h = bh & 15;
    const float il0 = 1.0f / l0;
    const float il1 = 1.0f / l1;
    const int mrow0 = b * SEQ + q0 + w * 16 + g;
#pragma unroll
    for (int nf = 0; nf < 16; nf++) {
        const int col = h * HDIM + nf * 8 + tg * 2;
        *(float2*)&O[(size_t)mrow0 * HIDDEN + col] =
            make_float2(oacc[nf][0] * il0, oacc[nf][1] * il0);
        *(float2*)&O[(size_t)(mrow0 + 8) * HIDDEN + col] =
            make_float2(oacc[nf][2] * il1, oacc[nf][3] * il1);
    }
}

// ============================================================================
// kernel_launch
// ============================================================================
extern "C" void kernel_launch(void* const* d_in, const int* in_sizes, int n_in,
                              void* d_out, int out_size) {
    (void)in_sizes; (void)n_in; (void)out_size;
    const float* x  = (const float*)d_in[0];
    const float* wq = (const float*)d_in[1];
    const float* wk = (const float*)d_in[2];
    const float* wv = (const float*)d_in[3];
    const float* wo = (const float*)d_in[4];
    float* out = (float*)d_out;

    float *q, *k, *v, *o;
    cudaGetSymbolAddress((void**)&q, g_q);
    cudaGetSymbolAddress((void**)&k, g_k);
    cudaGetSymbolAddress((void**)&v, g_v);
    cudaGetSymbolAddress((void**)&o, g_o);

    const dim3 gridP(HIDDEN / 128, MTOK / 128);   // (16, 32)

    hgemm3<1><<<gridP, 256>>>(x, wq, q);
    hgemm3<1><<<gridP, 256>>>(x, wk, k);
    hgemm3<1><<<gridP, 256>>>(x, wv, v);

    rope_kernel<<<BATCH * NHEADS * SEQ, 64>>>(q, k);

    static int attn_attr_set = 0;
    if (!attn_attr_set) {
        cudaFuncSetAttribute(flash_attn_h,
                             cudaFuncAttributeMaxDynamicSharedMemorySize,
                             AT_SMEM_BYTES);
        attn_attr_set = 1;
    }
    flash_attn_h<<<dim3(SEQ / 128, BATCH * NHEADS), 256, AT_SMEM_BYTES>>>(q, k, v, o);

    hgemm3<0><<<gridP, 256>>>(o, wo, out);
}

// round 5
// speedup vs baseline: 3.3203x; 1.4526x over previous
#include <cuda_runtime.h>
#include <cuda_fp16.h>
#include <math.h>
#include <stdint.h>

#define HIDDEN  2048
#define NHEADS  16
#define HDIM    128
#define BATCH   2
#define SEQ     2048
#define MTOK    (BATCH * SEQ)   // 4096

#define NELEM_X ((size_t)MTOK * HIDDEN)     // 8388608
#define NELEM_W ((size_t)HIDDEN * HIDDEN)   // 4194304

// ---------------- scratch (static device globals) ---------------------------
__device__ __align__(16) float  g_q[NELEM_X];
__device__ __align__(16) float  g_k[NELEM_X];
__device__ __align__(16) __half g_xh[NELEM_X],  g_xl[NELEM_X];
__device__ __align__(16) __half g_wqh[NELEM_W], g_wql[NELEM_W];
__device__ __align__(16) __half g_wkh[NELEM_W], g_wkl[NELEM_W];
__device__ __align__(16) __half g_wvh[NELEM_W], g_wvl[NELEM_W];
__device__ __align__(16) __half g_woh[NELEM_W], g_wol[NELEM_W];
__device__ __align__(16) __half g_qh[NELEM_X],  g_ql[NELEM_X];
__device__ __align__(16) __half g_kh[NELEM_X],  g_kl[NELEM_X];
__device__ __align__(16) __half g_vh[NELEM_X],  g_vl[NELEM_X];
__device__ __align__(16) __half g_oh[NELEM_X],  g_ol[NELEM_X];

// ---------------- helpers ----------------------------------------------------
__device__ __forceinline__ void split2(float x, float y, uint32_t& hi, uint32_t& lo) {
    __half2 h = __float22half2_rn(make_float2(x, y));
    float2 b = __half22float2(h);
    __half2 l = __float22half2_rn(make_float2(x - b.x, y - b.y));
    hi = *(uint32_t*)&h;
    lo = *(uint32_t*)&l;
}
__device__ __forceinline__ void mma16816(float* c, const uint32_t* a,
                                         uint32_t b0, uint32_t b1) {
    asm volatile(
        "mma.sync.aligned.m16n8k16.row.col.f32.f16.f16.f32 "
        "{%0,%1,%2,%3}, {%4,%5,%6,%7}, {%8,%9}, {%0,%1,%2,%3};\n"
        : "+f"(c[0]), "+f"(c[1]), "+f"(c[2]), "+f"(c[3])
        : "r"(a[0]), "r"(a[1]), "r"(a[2]), "r"(a[3]), "r"(b0), "r"(b1));
}
__device__ __forceinline__ uint32_t smem_u32(const void* p) {
    uint32_t a;
    asm("{ .reg .u64 t; cvta.to.shared.u64 t, %1; cvt.u32.u64 %0, t; }"
        : "=r"(a) : "l"(p));
    return a;
}
#define CP16(dst, src) \
    asm volatile("cp.async.cg.shared.global [%0], [%1], 16;" \
                 :: "r"(dst), "l"(src) : "memory")
#define CP_COMMIT() asm volatile("cp.async.commit_group;" ::: "memory")
#define CP_WAIT0()  asm volatile("cp.async.wait_group 0;"  ::: "memory")

// ============================================================================
// split kernels: fp32 array -> hi/lo fp16 arrays
// ============================================================================
__global__ __launch_bounds__(256) void split_kernel(const float4* __restrict__ src,
                                                    uint2* __restrict__ hi,
                                                    uint2* __restrict__ lo, int n4) {
    const int i = blockIdx.x * 256 + threadIdx.x;
    if (i >= n4) return;
    const float4 v = src[i];
    uint32_t h0, l0, h1, l1;
    split2(v.x, v.y, h0, l0);
    split2(v.z, v.w, h1, l1);
    hi[i] = make_uint2(h0, h1);
    lo[i] = make_uint2(l0, l1);
}

// ============================================================================
// GEMM core (NT): C = A @ B^T, A/B pre-split fp16 hi/lo [*,2048] row-major.
// 128x128 tile, BK=32, 256 threads, cp.async double-buffered.
// smem stage = {Ah,Al,Bh,Bl} x 128row x 20 words = 40960 B; 2 stages = 81920 B.
// ============================================================================
#define GK_SMEM 81920

__device__ __forceinline__ void g_fill(uint32_t sb,
                                       const __half* __restrict__ Ah,
                                       const __half* __restrict__ Al,
                                       const __half* __restrict__ Bh,
                                       const __half* __restrict__ Bl,
                                       int bm, int bn, int k0) {
    const int tid = threadIdx.x;
    const int row = tid >> 1, hf = tid & 1;
    const uint32_t off = (uint32_t)(row * 20 + hf * 8) * 4;
    const size_t ra = ((size_t)(bm + row) << 11) + k0 + hf * 16;
    const size_t rb = ((size_t)(bn + row) << 11) + k0 + hf * 16;
    CP16(sb + off,         Ah + ra); CP16(sb + off + 16,         Ah + ra + 8);
    CP16(sb + 10240 + off, Al + ra); CP16(sb + 10240 + off + 16, Al + ra + 8);
    CP16(sb + 20480 + off, Bh + rb); CP16(sb + 20480 + off + 16, Bh + rb + 8);
    CP16(sb + 30720 + off, Bl + rb); CP16(sb + 30720 + off + 16, Bl + rb + 8);
}

__device__ __forceinline__ void g_compute(const uint32_t* __restrict__ s,
                                          float acc[4][4][4],
                                          int wm, int wn, int g, int tg) {
    const uint32_t* sAh = s;
    const uint32_t* sAl = s + 2560;
    const uint32_t* sBh = s + 5120;
    const uint32_t* sBl = s + 7680;
#pragma unroll
    for (int ks = 0; ks < 2; ks++) {
        const int base = ks * 8 + tg;
        uint32_t ah[4][4], al[4][4];
#pragma unroll
        for (int mf = 0; mf < 4; mf++) {
            const int r = wm * 64 + mf * 16 + g;
            ah[mf][0] = sAh[r * 20 + base];
            ah[mf][1] = sAh[(r + 8) * 20 + base];
            ah[mf][2] = sAh[r * 20 + base + 4];
            ah[mf][3] = sAh[(r + 8) * 20 + base + 4];
            al[mf][0] = sAl[r * 20 + base];
            al[mf][1] = sAl[(r + 8) * 20 + base];
            al[mf][2] = sAl[r * 20 + base + 4];
            al[mf][3] = sAl[(r + 8) * 20 + base + 4];
        }
#pragma unroll
        for (int nf = 0; nf < 4; nf++) {
            const int n = wn * 32 + nf * 8 + g;
            const uint32_t bh0 = sBh[n * 20 + base];
            const uint32_t bh1 = sBh[n * 20 + base + 4];
            const uint32_t bl0 = sBl[n * 20 + base];
            const uint32_t bl1 = sBl[n * 20 + base + 4];
#pragma unroll
            for (int mf = 0; mf < 4; mf++) {
                mma16816(acc[mf][nf], ah[mf], bh0, bh1);
                mma16816(acc[mf][nf], al[mf], bh0, bh1);
                mma16816(acc[mf][nf], ah[mf], bl0, bl1);
            }
        }
    }
}

// Fused QKV GEMM: blockIdx.z selects weight/output.
// z=0 -> q fp32 [B,H,S,D]; z=1 -> k fp32 [B,H,S,D]; z=2 -> v split fp16 hi/lo.
__global__ __launch_bounds__(256, 2) void qkv_gemm(
    const __half* __restrict__ xh, const __half* __restrict__ xl,
    const __half* __restrict__ wqh, const __half* __restrict__ wql,
    const __half* __restrict__ wkh, const __half* __restrict__ wkl,
    const __half* __restrict__ wvh, const __half* __restrict__ wvl,
    float* __restrict__ q, float* __restrict__ k,
    uint32_t* __restrict__ vh, uint32_t* __restrict__ vl) {
    extern __shared__ uint32_t dyn[];
    const int tid = threadIdx.x;
    const int w = tid >> 5, lane = tid & 31;
    const int g = lane >> 2, tg = lane & 3;
    const int wm = w >> 2, wn = w & 3;
    const int bm = blockIdx.y * 128, bn = blockIdx.x * 128;
    const int z = blockIdx.z;

    const __half* Bh = (z == 0) ? wqh : (z == 1) ? wkh : wvh;
    const __half* Bl = (z == 0) ? wql : (z == 1) ? wkl : wvl;

    float acc[4][4][4];
#pragma unroll
    for (int i = 0; i < 4; i++)
#pragma unroll
        for (int j = 0; j < 4; j++)
#pragma unroll
            for (int c = 0; c < 4; c++) acc[i][j][c] = 0.0f;

    const uint32_t sb = smem_u32(dyn);
    g_fill(sb, xh, xl, Bh, Bl, bm, bn, 0);
    CP_COMMIT();

    for (int i = 0; i < 64; i++) {
        CP_WAIT0();
        __syncthreads();
        if (i + 1 < 64) {
            g_fill(sb + ((i + 1) & 1) * 40960u, xh, xl, Bh, Bl, bm, bn, (i + 1) * 32);
            CP_COMMIT();
        }
        g_compute(dyn + (i & 1) * 10240, acc, wm, wn, g, tg);
    }

    // epilogue
#pragma unroll
    for (int mf = 0; mf < 4; mf++) {
#pragma unroll
        for (int nf = 0; nf < 4; nf++) {
            const int n = bn + wn * 32 + nf * 8 + tg * 2;
            const int h = n >> 7, d = n & 127;
            const int m0 = bm + wm * 64 + mf * 16 + g;
            const int b = m0 >> 11, s0 = m0 & (SEQ - 1);
            if (z == 2) {
                const size_t widx =
                    (((size_t)(b * NHEADS + h) * SEQ + s0) << 6) + (d >> 1);
                uint32_t hi, lo;
                split2(acc[mf][nf][0], acc[mf][nf][1], hi, lo);
                vh[widx] = hi; vl[widx] = lo;
                split2(acc[mf][nf][2], acc[mf][nf][3], hi, lo);
                vh[widx + 512] = hi; vl[widx + 512] = lo;   // row +8 -> +8*64
            } else {
                float* C = (z == 0) ? q : k;
                const size_t base =
                    (((size_t)(b * NHEADS + h) * SEQ + s0) << 7) + d;
                *(float2*)&C[base] = make_float2(acc[mf][nf][0], acc[mf][nf][1]);
                *(float2*)&C[base + (8u << 7)] =
                    make_float2(acc[mf][nf][2], acc[mf][nf][3]);
            }
        }
    }
}

// Output GEMM: A = o split fp16, B = wo split fp16, C = fp32 row-major.
__global__ __launch_bounds__(256, 2) void out_gemm(
    const __half* __restrict__ Ah, const __half* __restrict__ Al,
    const __half* __restrict__ Bh, const __half* __restrict__ Bl,
    float* __restrict__ C) {
    extern __shared__ uint32_t dyn[];
    const int tid = threadIdx.x;
    const int w = tid >> 5, lane = tid & 31;
    const int g = lane >> 2, tg = lane & 3;
    const int wm = w >> 2, wn = w & 3;
    const int bm = blockIdx.y * 128, bn = blockIdx.x * 128;

    float acc[4][4][4];
#pragma unroll
    for (int i = 0; i < 4; i++)
#pragma unroll
        for (int j = 0; j < 4; j++)
#pragma unroll
            for (int c = 0; c < 4; c++) acc[i][j][c] = 0.0f;

    const uint32_t sb = smem_u32(dyn);
    g_fill(sb, Ah, Al, Bh, Bl, bm, bn, 0);
    CP_COMMIT();

    for (int i = 0; i < 64; i++) {
        CP_WAIT0();
        __syncthreads();
        if (i + 1 < 64) {
            g_fill(sb + ((i + 1) & 1) * 40960u, Ah, Al, Bh, Bl, bm, bn, (i + 1) * 32);
            CP_COMMIT();
        }
        g_compute(dyn + (i & 1) * 10240, acc, wm, wn, g, tg);
    }

#pragma unroll
    for (int mf = 0; mf < 4; mf++) {
#pragma unroll
        for (int nf = 0; nf < 4; nf++) {
            const int n = bn + wn * 32 + nf * 8 + tg * 2;
#pragma unroll
            for (int half = 0; half < 2; half++) {
                const int m = bm + wm * 64 + mf * 16 + g + half * 8;
                *(float2*)&C[(size_t)m * HIDDEN + n] =
                    make_float2(acc[mf][nf][half * 2], acc[mf][nf][half * 2 + 1]);
            }
        }
    }
}

// ============================================================================
// RoPE: fp32 q,k [B,H,S,D] -> split fp16 (q scaled by 1/sqrt(D)).
// thread handles d-pairs (2j,2j+1) and (2j+64,2j+65) of one row.
// ============================================================================
__global__ __launch_bounds__(256) void rope_split(
    const float* __restrict__ q, const float* __restrict__ k,
    uint32_t* __restrict__ qh, uint32_t* __restrict__ ql,
    uint32_t* __restrict__ kh, uint32_t* __restrict__ kl) {
    const int gt = blockIdx.x * 256 + threadIdx.x;
    const int row = gt >> 5;
    const int j = gt & 31;
    const int s = row & (SEQ - 1);
    const float sc = 0.08838834764831845f;   // 1/sqrt(128)

    const int p0 = 2 * j, p1 = 2 * j + 1;
    const float i0 = powf(10000.0f, -(float)(2 * p0) / 128.0f);
    const float i1 = powf(10000.0f, -(float)(2 * p1) / 128.0f);
    float sn0, cs0, sn1, cs1;
    sincosf((float)s * i0, &sn0, &cs0);
    sincosf((float)s * i1, &sn1, &cs1);

    const float* pq = q + (size_t)row * HDIM;
    const float* pk = k + (size_t)row * HDIM;
    const float2 qa = *(const float2*)(pq + p0);
    const float2 qb = *(const float2*)(pq + p0 + 64);
    const float2 ka = *(const float2*)(pk + p0);
    const float2 kb = *(const float2*)(pk + p0 + 64);

    const float ql0 = qa.x * cs0 - qb.x * sn0;
    const float ql1 = qa.y * cs1 - qb.y * sn1;
    const float qh0 = qb.x * cs0 + qa.x * sn0;
    const float qh1 = qb.y * cs1 + qa.y * sn1;
    const float kl0 = ka.x * cs0 - kb.x * sn0;
    const float kl1 = ka.y * cs1 - kb.y * sn1;
    const float kh0 = kb.x * cs0 + ka.x * sn0;
    const float kh1 = kb.y * cs1 + ka.y * sn1;

    uint32_t hi, lo;
    const size_t wbase = (size_t)row * 64;
    split2(ql0 * sc, ql1 * sc, hi, lo); qh[wbase + j] = hi;      ql[wbase + j] = lo;
    split2(qh0 * sc, qh1 * sc, hi, lo); qh[wbase + 32 + j] = hi; ql[wbase + 32 + j] = lo;
    split2(kl0, kl1, hi, lo); kh[wbase + j] = hi;      kl[wbase + j] = lo;
    split2(kh0, kh1, hi, lo); kh[wbase + 32 + j] = hi; kl[wbase + 32 + j] = lo;
}

// ============================================================================
// Flash attention, split-fp16 3-pass mma.sync, preconverted Q/K/V.
// grid (SEQ/128, B*H), 256 threads = 8 warps; warp owns 16 q rows.
// ============================================================================
#define AT_KH  0
#define AT_KL  (64 * 68)
#define AT_VH  (2 * 64 * 68)
#define AT_VL  (2 * 64 * 68 + 128 * 36)
#define AT_P   (2 * 64 * 68 + 2 * 128 * 36)
#define AT_SMEM_WORDS (AT_P + 8 * 2 * 16 * 36)
#define AT_SMEM_BYTES (AT_SMEM_WORDS * 4)

__global__ __launch_bounds__(256) void flash_attn_h(
    const uint32_t* __restrict__ QH, const uint32_t* __restrict__ QL,
    const uint32_t* __restrict__ KHg, const uint32_t* __restrict__ KLg,
    const uint32_t* __restrict__ VHg, const uint32_t* __restrict__ VLg,
    uint32_t* __restrict__ OH, uint32_t* __restrict__ OL) {
    extern __shared__ uint32_t su[];
    uint32_t* Kh2 = su + AT_KH;
    uint32_t* Kl2 = su + AT_KL;
    uint32_t* Vh2 = su + AT_VH;
    uint32_t* Vl2 = su + AT_VL;

    const int tid = threadIdx.x;
    const int w = tid >> 5, lane = tid & 31;
    const int g = lane >> 2, tg = lane & 3;
    uint32_t* Ph2 = su + AT_P + w * (2 * 16 * 36);
    uint32_t* Pl2 = Ph2 + 16 * 36;

    const int bh = blockIdx.y;
    const int q0 = blockIdx.x * 128;

    // ---- Q fragments: direct u32 loads (scale already folded in) ----
    uint32_t qh[8][4], ql[8][4];
    {
        const uint32_t* Qh = QH + ((size_t)bh * SEQ + q0 + w * 16) * 64;
        const uint32_t* Ql = QL + ((size_t)bh * SEQ + q0 + w * 16) * 64;
#pragma unroll
        for (int ks = 0; ks < 8; ks++) {
            const int base = ks * 8 + tg;
            qh[ks][0] = Qh[g * 64 + base];
            qh[ks][1] = Qh[(g + 8) * 64 + base];
            qh[ks][2] = Qh[g * 64 + base + 4];
            qh[ks][3] = Qh[(g + 8) * 64 + base + 4];
            ql[ks][0] = Ql[g * 64 + base];
            ql[ks][1] = Ql[(g + 8) * 64 + base];
            ql[ks][2] = Ql[g * 64 + base + 4];
            ql[ks][3] = Ql[(g + 8) * 64 + base + 4];
        }
    }

    float m0 = -1e30f, m1 = -1e30f, l0 = 0.0f, l1 = 0.0f;
    float oacc[16][4];
#pragma unroll
    for (int nf = 0; nf < 16; nf++)
#pragma unroll
        for (int c = 0; c < 4; c++) oacc[nf][c] = 0.0f;

    for (int kt = 0; kt < SEQ / 64; kt++) {
        __syncthreads();   // previous iteration's smem reads complete

        // ---- K tile: straight copy [key][d2], stride 68 ----
        {
            const uint32_t* Kh = KHg + ((size_t)bh * SEQ + kt * 64) * 64;
            const uint32_t* Kl = KLg + ((size_t)bh * SEQ + kt * 64) * 64;
            const int row = tid >> 2, q4 = tid & 3;
#pragma unroll
            for (int i = 0; i < 4; i++) {
                const int wo = q4 * 4 + i * 16;
                *(uint4*)&Kh2[row * 68 + wo] = *(const uint4*)&Kh[row * 64 + wo];
                *(uint4*)&Kl2[row * 68 + wo] = *(const uint4*)&Kl[row * 64 + wo];
            }
        }
        // ---- V tile: repack d-pairs -> key-pairs, [d][key2], stride 36 ----
        {
            const uint32_t* Vh = VHg + ((size_t)bh * SEQ + kt * 64) * 64;
            const uint32_t* Vl = VLg + ((size_t)bh * SEQ + kt * 64) * 64;
            const int e = tid & 63, kg = tid >> 6;
#pragma unroll
            for (int j = 0; j < 8; j++) {
                const int k2 = kg * 8 + j;
                uint32_t w0 = Vh[(2 * k2) * 64 + e];
                uint32_t w1 = Vh[(2 * k2 + 1) * 64 + e];
                Vh2[(2 * e) * 36 + k2]     = __byte_perm(w0, w1, 0x5410);
                Vh2[(2 * e + 1) * 36 + k2] = __byte_perm(w0, w1, 0x7632);
                w0 = Vl[(2 * k2) * 64 + e];
                w1 = Vl[(2 * k2 + 1) * 64 + e];
                Vl2[(2 * e) * 36 + k2]     = __byte_perm(w0, w1, 0x5410);
                Vl2[(2 * e + 1) * 36 + k2] = __byte_perm(w0, w1, 0x7632);
            }
        }
        __syncthreads();

        // ---- S = Q K^T ----
        float sacc[8][4];
#pragma unroll
        for (int nf = 0; nf < 8; nf++)
#pragma unroll
            for (int c = 0; c < 4; c++) sacc[nf][c] = 0.0f;

#pragma unroll
        for (int ks = 0; ks < 8; ks++) {
#pragma unroll
            for (int nf = 0; nf < 8; nf++) {
                const int ad = (nf * 8 + g) * 68 + ks * 8 + tg;
                const uint32_t bh0 = Kh2[ad], bh1 = Kh2[ad + 4];
                const uint32_t bl0 = Kl2[ad], bl1 = Kl2[ad + 4];
                mma16816(sacc[nf], qh[ks], bh0, bh1);
                mma16816(sacc[nf], ql[ks], bh0, bh1);
                mma16816(sacc[nf], qh[ks], bl0, bl1);
            }
        }

        // ---- online softmax ----
        float mx0 = -1e30f, mx1 = -1e30f;
#pragma unroll
        for (int nf = 0; nf < 8; nf++) {
            mx0 = fmaxf(mx0, fmaxf(sacc[nf][0], sacc[nf][1]));
            mx1 = fmaxf(mx1, fmaxf(sacc[nf][2], sacc[nf][3]));
        }
        mx0 = fmaxf(mx0, __shfl_xor_sync(0xffffffffu, mx0, 1));
        mx0 = fmaxf(mx0, __shfl_xor_sync(0xffffffffu, mx0, 2));
        mx1 = fmaxf(mx1, __shfl_xor_sync(0xffffffffu, mx1, 1));
        mx1 = fmaxf(mx1, __shfl_xor_sync(0xffffffffu, mx1, 2));

        const float mn0 = fmaxf(m0, mx0);
        const float mn1 = fmaxf(m1, mx1);
        const float fi0 = __expf(m0 - mn0);
        const float fi1 = __expf(m1 - mn1);
        m0 = mn0; m1 = mn1;

        float sum0 = 0.0f, sum1 = 0.0f;
#pragma unroll
        for (int nf = 0; nf < 8; nf++) {
            sacc[nf][0] = __expf(sacc[nf][0] - mn0);
            sacc[nf][1] = __expf(sacc[nf][1] - mn0);
            sacc[nf][2] = __expf(sacc[nf][2] - mn1);
            sacc[nf][3] = __expf(sacc[nf][3] - mn1);
            sum0 += sacc[nf][0] + sacc[nf][1];
            sum1 += sacc[nf][2] + sacc[nf][3];
        }
        sum0 += __shfl_xor_sync(0xffffffffu, sum0, 1);
        sum0 += __shfl_xor_sync(0xffffffffu, sum0, 2);
        sum1 += __shfl_xor_sync(0xffffffffu, sum1, 1);
        sum1 += __shfl_xor_sync(0xffffffffu, sum1, 2);
        l0 = l0 * fi0 + sum0;
        l1 = l1 * fi1 + sum1;

#pragma unroll
        for (int nf = 0; nf < 16; nf++) {
            oacc[nf][0] *= fi0; oacc[nf][1] *= fi0;
            oacc[nf][2] *= fi1; oacc[nf][3] *= fi1;
        }

        // ---- write split P (warp-private) ----
#pragma unroll
        for (int nf = 0; nf < 8; nf++) {
            uint32_t hi, lo;
            split2(sacc[nf][0], sacc[nf][1], hi, lo);
            Ph2[g * 36 + nf * 4 + tg] = hi;
            Pl2[g * 36 + nf * 4 + tg] = lo;
            split2(sacc[nf][2], sacc[nf][3], hi, lo);
            Ph2[(g + 8) * 36 + nf * 4 + tg] = hi;
            Pl2[(g + 8) * 36 + nf * 4 + tg] = lo;
        }
        __syncwarp();

        // ---- O += P @ V ----
#pragma unroll
        for (int ks = 0; ks < 4; ks++) {
            uint32_t pa[4], pl[4];
            const int base = ks * 8 + tg;
            pa[0] = Ph2[g * 36 + base];
            pa[1] = Ph2[(g + 8) * 36 + base];
            pa[2] = Ph2[g * 36 + base + 4];
            pa[3] = Ph2[(g + 8) * 36 + base + 4];
            pl[0] = Pl2[g * 36 + base];
            pl[1] = Pl2[(g + 8) * 36 + base];
            pl[2] = Pl2[g * 36 + base + 4];
            pl[3] = Pl2[(g + 8) * 36 + base + 4];
#pragma unroll
            for (int nf = 0; nf < 16; nf++) {
                const int ad = (nf * 8 + g) * 36 + base;
                const uint32_t bh0 = Vh2[ad], bh1 = Vh2[ad + 4];
                const uint32_t bl0 = Vl2[ad], bl1 = Vl2[ad + 4];
                mma16816(oacc[nf], pa, bh0, bh1);
                mma16816(oacc[nf], pl, bh0, bh1);
                mma16816(oacc[nf], pa, bl0, bl1);
            }
        }
    }

    // ---- epilogue: O/l -> split fp16, token-major [B*S, H*D] ----
    const int b = bh >> 4;
    const int h = bh & 15;
    const float il0 = 1.0f / l0;
    const float il1 = 1.0f / l1;
    const int mrow0 = b * SEQ + q0 + w * 16 + g;
#pragma unroll
    for (int nf = 0; nf < 16; nf++) {
        const int cw = h * 64 + nf * 4 + tg;   // u32 word column
        uint32_t hi, lo;
        split2(oacc[nf][0] * il0, oacc[nf][1] * il0, hi, lo);
        OH[(size_t)mrow0 * 1024 + cw] = hi;
        OL[(size_t)mrow0 * 1024 + cw] = lo;
        split2(oacc[nf][2] * il1, oacc[nf][3] * il1, hi, lo);
        OH[(size_t)(mrow0 + 8) * 1024 + cw] = hi;
        OL[(size_t)(mrow0 + 8) * 1024 + cw] = lo;
    }
}

// ============================================================================
// kernel_launch
// ============================================================================
extern "C" void kernel_launch(void* const* d_in, const int* in_sizes, int n_in,
                              void* d_out, int out_size) {
    (void)in_sizes; (void)n_in; (void)out_size;
    const float* x  = (const float*)d_in[0];
    const float* wq = (const float*)d_in[1];
    const float* wk = (const float*)d_in[2];
    const float* wv = (const float*)d_in[3];
    const float* wo = (const float*)d_in[4];
    float* out = (float*)d_out;

    void *q, *k, *xh, *xl, *wqh, *wql, *wkh, *wkl, *wvh, *wvl, *woh, *wol;
    void *qh, *ql, *kh, *kl, *vh, *vl, *oh, *ol;
    cudaGetSymbolAddress(&q, g_q);    cudaGetSymbolAddress(&k, g_k);
    cudaGetSymbolAddress(&xh, g_xh);  cudaGetSymbolAddress(&xl, g_xl);
    cudaGetSymbolAddress(&wqh, g_wqh); cudaGetSymbolAddress(&wql, g_wql);
    cudaGetSymbolAddress(&wkh, g_wkh); cudaGetSymbolAddress(&wkl, g_wkl);
    cudaGetSymbolAddress(&wvh, g_wvh); cudaGetSymbolAddress(&wvl, g_wvl);
    cudaGetSymbolAddress(&woh, g_woh); cudaGetSymbolAddress(&wol, g_wol);
    cudaGetSymbolAddress(&qh, g_qh);  cudaGetSymbolAddress(&ql, g_ql);
    cudaGetSymbolAddress(&kh, g_kh);  cudaGetSymbolAddress(&kl, g_kl);
    cudaGetSymbolAddress(&vh, g_vh);  cudaGetSymbolAddress(&vl, g_vl);
    cudaGetSymbolAddress(&oh, g_oh);  cudaGetSymbolAddress(&ol, g_ol);

    cudaFuncSetAttribute(qkv_gemm,
                         cudaFuncAttributeMaxDynamicSharedMemorySize, GK_SMEM);
    cudaFuncSetAttribute(out_gemm,
                         cudaFuncAttributeMaxDynamicSharedMemorySize, GK_SMEM);
    cudaFuncSetAttribute(flash_attn_h,
                         cudaFuncAttributeMaxDynamicSharedMemorySize, AT_SMEM_BYTES);

    // 1. pre-split x and weights
    split_kernel<<<(int)(NELEM_X / 4 / 256), 256>>>(
        (const float4*)x, (uint2*)xh, (uint2*)xl, (int)(NELEM_X / 4));
    split_kernel<<<(int)(NELEM_W / 4 / 256), 256>>>(
        (const float4*)wq, (uint2*)wqh, (uint2*)wql, (int)(NELEM_W / 4));
    split_kernel<<<(int)(NELEM_W / 4 / 256), 256>>>(
        (const float4*)wk, (uint2*)wkh, (uint2*)wkl, (int)(NELEM_W / 4));
    split_kernel<<<(int)(NELEM_W / 4 / 256), 256>>>(
        (const float4*)wv, (uint2*)wvh, (uint2*)wvl, (int)(NELEM_W / 4));
    split_kernel<<<(int)(NELEM_W / 4 / 256), 256>>>(
        (const float4*)wo, (uint2*)woh, (uint2*)wol, (int)(NELEM_W / 4));

    // 2. fused QKV projections
    qkv_gemm<<<dim3(HIDDEN / 128, MTOK / 128, 3), 256, GK_SMEM>>>(
        (const __half*)xh, (const __half*)xl,
        (const __half*)wqh, (const __half*)wql,
        (const __half*)wkh, (const __half*)wkl,
        (const __half*)wvh, (const __half*)wvl,
        (float*)q, (float*)k, (uint32_t*)vh, (uint32_t*)vl);

    // 3. RoPE + split
    rope_split<<<(BATCH * NHEADS * SEQ * 32) / 256, 256>>>(
        (const float*)q, (const float*)k,
        (uint32_t*)qh, (uint32_t*)ql, (uint32_t*)kh, (uint32_t*)kl);

    // 4. attention
    flash_attn_h<<<dim3(SEQ / 128, BATCH * NHEADS), 256, AT_SMEM_BYTES>>>(
        (const uint32_t*)qh, (const uint32_t*)ql,
        (const uint32_t*)kh, (const uint32_t*)kl,
        (const uint32_t*)vh, (const uint32_t*)vl,
        (uint32_t*)oh, (uint32_t*)ol);

    // 5. output projection
    out_gemm<<<dim3(HIDDEN / 128, MTOK / 128), 256, GK_SMEM>>>(
        (const __half*)oh, (const __half*)ol,
        (const __half*)woh, (const __half*)wol, out);
}